// round 6
// baseline (speedup 1.0000x reference)
#include <cuda_runtime.h>
#include <math.h>

#define NB   8
#define NN   512
#define FF   8
#define FP   16
#define NH1  64
#define NH2  32
#define NS   2
#define TIT  10
#define JT   128          // j-tile size
#define NTILE (NN/JT)     // 4
#define BPAD 68           // padded row stride (floats) for B tile in smem

// ---------------- scratch (no allocations allowed) ----------------
__device__ __align__(256) float g_A  [NB*NN*NH1];   // u_i @ W1a + sigma*w1s + b1
__device__ __align__(256) float g_Bm [NB*NN*NH1];   // u_j @ W1b
__device__ __align__(256) float g_si [NB*NN];
__device__ __align__(256) float g_sj [NB*NN];
__device__ __align__(256) float g_mx [NB*NN];
__device__ __align__(256) float g_invd[NB*NN];
__device__ __align__(256) float g_gh [NB*NN*24];    // u @ Whh + bhh
__device__ __align__(256) float g_u  [2][NB*NN*FF]; // ping-pong state
__device__ __align__(256) unsigned short g_nbr[NB*NN*NN]; // compacted neighbor idx (sorted)
__device__ __align__(256) float g_ec [NB*NN*NN];    // compacted edge feat
__device__ __align__(256) int   g_cnt[NB*NN];
__device__ __align__(256) int   g_toff[NB*NN*5];    // per-row tile offsets {0,b1,b2,b3,cnt}

// ---------------- adjacency compaction (runs once; adj static) ----------------
__global__ void k_compact(const int* __restrict__ adj, const float* __restrict__ ef)
{
    int warp = (blockIdx.x * blockDim.x + threadIdx.x) >> 5;
    int lane = threadIdx.x & 31;
    if (warp >= NB*NN) return;
    const int*   arow = adj + (size_t)warp * NN;
    const float* erow = ef  + (size_t)warp * NN;
    int base = 0;
    int t1 = 0, t2 = 0, t3 = 0;
    #pragma unroll
    for (int c = 0; c < NN/32; c++) {
        if (c == 4)  t1 = base;
        if (c == 8)  t2 = base;
        if (c == 12) t3 = base;
        int jj = c*32 + lane;
        int a  = arow[jj];
        unsigned bal = __ballot_sync(0xffffffffu, a > 0);
        if (a > 0) {
            int pos = base + __popc(bal & ((1u << lane) - 1u));
            g_nbr[(size_t)warp*NN + pos] = (unsigned short)jj;
            g_ec [(size_t)warp*NN + pos] = erow[jj];
        }
        base += __popc(bal);
    }
    if (lane == 0) {
        g_cnt[warp] = base;
        g_toff[warp*5 + 0] = 0;
        g_toff[warp*5 + 1] = t1;
        g_toff[warp*5 + 2] = t2;
        g_toff[warp*5 + 3] = t3;
        g_toff[warp*5 + 4] = base;
    }
}

// ---------------- per-node precompute ----------------
__global__ void k_node(const float* __restrict__ u0,
                       const float* __restrict__ Wattn,
                       const float* __restrict__ al, const float* __restrict__ ar,
                       const float* __restrict__ W1, const float* __restrict__ b1,
                       const float* __restrict__ Whh, const float* __restrict__ bhh,
                       const float* __restrict__ sigma2, int t)
{
    __shared__ float sWa[FF*FP], sal[FP], sar[FP];
    __shared__ float sW1a[FF*NH1], sW1b[FF*NH1], sw1s[NH1], sb1[NH1];
    __shared__ float sWhh[FF*24], sbhh[24];
    int tid = threadIdx.x;
    for (int x = tid; x < FF*FP; x += blockDim.x) sWa[x] = Wattn[x];
    if (tid < FP) { sal[tid] = al[tid]; sar[tid] = ar[tid]; }
    for (int x = tid; x < FF*NH1; x += blockDim.x) {
        sW1a[x] = W1[x];
        sW1b[x] = W1[FF*NH1 + x];
    }
    if (tid < NH1) { sw1s[tid] = W1[17*NH1 + tid]; sb1[tid] = b1[tid]; }
    for (int x = tid; x < FF*24; x += blockDim.x) sWhh[x] = Whh[x];
    if (tid < 24) sbhh[tid] = bhh[tid];
    __syncthreads();

    int node = blockIdx.x * blockDim.x + tid;   // 4096 nodes
    int b = node >> 9;
    const float* uin = (t == 0) ? u0 : g_u[t & 1];
    float u[FF];
    #pragma unroll
    for (int x = 0; x < FF; x++) u[x] = uin[node*FF + x];
    float sg = sigma2[b];

    // attention scores (split-a)
    float si = 0.f, sj = 0.f;
    #pragma unroll
    for (int p = 0; p < FP; p++) {
        float acc = 0.f;
        #pragma unroll
        for (int x = 0; x < FF; x++) acc = fmaf(u[x], sWa[x*FP + p], acc);
        si = fmaf(acc, sal[p], si);
        sj = fmaf(acc, sar[p], sj);
    }
    g_si[node] = si; g_sj[node] = sj;

    // A/B rows
    for (int m = 0; m < NH1; m++) {
        float a  = fmaf(sg, sw1s[m], sb1[m]);
        float bb = 0.f;
        #pragma unroll
        for (int x = 0; x < FF; x++) {
            a  = fmaf(u[x], sW1a[x*NH1 + m], a);
            bb = fmaf(u[x], sW1b[x*NH1 + m], bb);
        }
        g_A [(size_t)node*NH1 + m] = a;
        g_Bm[(size_t)node*NH1 + m] = bb;
    }
    // gh = u @ Whh + bhh
    for (int g = 0; g < 24; g++) {
        float acc = sbhh[g];
        #pragma unroll
        for (int x = 0; x < FF; x++) acc = fmaf(u[x], sWhh[x*24 + g], acc);
        g_gh[(size_t)node*24 + g] = acc;
    }
}

// ---------------- softmax stats per row ----------------
__global__ void k_soft()
{
    int warp = (blockIdx.x * blockDim.x + threadIdx.x) >> 5;
    int lane = threadIdx.x & 31;
    if (warp >= NB*NN) return;
    int b = warp >> 9;
    int cnt = g_cnt[warp];
    float si = g_si[warp];
    const unsigned short* nb = g_nbr + (size_t)warp*NN;
    const float* sjb = g_sj + b*NN;

    float mx = -3.4e38f;
    for (int s = lane; s < cnt; s += 32) {
        float bt = si + sjb[nb[s]];
        bt = bt > 0.f ? bt : 0.2f*bt;
        mx = fmaxf(mx, bt);
    }
    #pragma unroll
    for (int o = 16; o; o >>= 1) mx = fmaxf(mx, __shfl_xor_sync(0xffffffffu, mx, o));
    float sm = 0.f;
    for (int s = lane; s < cnt; s += 32) {
        float bt = si + sjb[nb[s]];
        bt = bt > 0.f ? bt : 0.2f*bt;
        sm += __expf(bt - mx);
    }
    #pragma unroll
    for (int o = 16; o; o >>= 1) sm += __shfl_xor_sync(0xffffffffu, sm, o);
    if (lane == 0) {
        g_mx  [warp] = (cnt > 0) ? mx : 0.f;
        g_invd[warp] = (cnt > 0) ? (1.f/sm) : 0.f;
    }
}

// ---------------- fused edge MLP + aggregate + GRU ----------------
// block = 256 threads = 8 warps; warp w owns node i = i_base + w.
// j is tiled: B rows for a 128-j tile are staged into padded smem (coalesced
// LDG), so per-edge B gathers are LDS from the tile instead of 32-line
// scattered LDG. Edge lists are sorted so tile boundaries are precomputed.
// 2-edge-per-lane register blocking keeps the W2 LDS amortized.
// Layer-3 folded: agg = (sum_e a_e relu(h2_e)) @ W3 + b3*[cnt>0]
__global__ void __launch_bounds__(256, 2) k_edge(
    const float* __restrict__ u0,
    const float* __restrict__ W1,
    const float* __restrict__ W2, const float* __restrict__ b2,
    const float* __restrict__ W3, const float* __restrict__ b3,
    const float* __restrict__ Wih, const float* __restrict__ bih, int t)
{
    __shared__ __align__(16) float sW2[NH1*NH2];   // 8 KB
    __shared__ __align__(16) float sW3[NH2*FF];
    __shared__ __align__(16) float sA [8*NH1];
    __shared__ __align__(16) float sw1e[NH1];
    __shared__ __align__(16) float sBt[JT*BPAD];   // 34 KB j-tile of B
    __shared__ float sSj[JT];
    __shared__ float sb2[NH2], sb3[FF];
    __shared__ float s_si[8], s_mx[8], s_invd[8];
    __shared__ int   s_toff[8*5];
    __shared__ float sWih[FF*24], sbih[24];

    int tid = threadIdx.x;
    int bx  = blockIdx.x;
    int b   = bx >> 6;
    int i_base = (bx & 63) * 8;
    int rowbase = b*NN + i_base;

    for (int x = tid; x < NH1*NH2; x += 256) sW2[x] = W2[x];
    for (int x = tid; x < NH2*FF;  x += 256) sW3[x] = W3[x];
    if (tid < NH2) sb2[tid] = b2[tid];
    if (tid < FF)  sb3[tid] = b3[tid];
    if (tid < NH1) sw1e[tid] = W1[16*NH1 + tid];
    for (int x = tid; x < 8*NH1; x += 256) sA[x] = g_A[(size_t)rowbase*NH1 + x];
    if (tid < 8) {
        s_si  [tid] = g_si  [rowbase + tid];
        s_mx  [tid] = g_mx  [rowbase + tid];
        s_invd[tid] = g_invd[rowbase + tid];
    }
    if (tid < 40) s_toff[tid] = g_toff[rowbase*5 + tid];
    for (int x = tid; x < FF*24; x += 256) sWih[x] = Wih[x];
    if (tid < 24) sbih[tid] = bih[tid];

    int w    = tid >> 5;
    int lane = tid & 31;
    int row  = rowbase + w;

    // p = sum_e alpha_e * relu(h2_e)  (accumulated across all tiles)
    float p[NH2];
    #pragma unroll
    for (int k = 0; k < NH2; k++) p[k] = 0.f;

    const float4* sA4  = 0;
    const float4* we4  = reinterpret_cast<const float4*>(sw1e);
    const float4* sW24 = reinterpret_cast<const float4*>(sW2);
    const unsigned short* nb = g_nbr + (size_t)row*NN;
    const float* ec  = g_ec + (size_t)row*NN;

    for (int T = 0; T < NTILE; T++) {
        __syncthreads();   // prior tile fully consumed (also orders initial loads at T=0)
        // stage B tile + sj tile (coalesced)
        {
            const float* Bsrc = &g_Bm[(size_t)(b*NN + T*JT)*NH1];
            for (int x = tid; x < JT*NH1; x += 256) {
                int r = x >> 6, c = x & 63;
                sBt[r*BPAD + c] = Bsrc[x];
            }
            if (tid < JT) sSj[tid] = g_sj[b*NN + T*JT + tid];
        }
        __syncthreads();

        sA4 = reinterpret_cast<const float4*>(&sA[w*NH1]);
        float si = s_si[w], mx = s_mx[w], invd = s_invd[w];
        int sBeg = s_toff[w*5 + T];
        int sEnd = s_toff[w*5 + T + 1];
        int jsub = T*JT;

        for (int s0 = sBeg + lane; s0 < sEnd; s0 += 64) {
            int  s1ok = (s0 + 32) < sEnd;
            int  j0   = nb[s0] - jsub;
            int  j1   = s1ok ? (nb[s0 + 32] - jsub) : j0;
            float e0  = ec[s0];
            float e1  = s1ok ? ec[s0 + 32] : 0.f;
            const float4* Bp0 = reinterpret_cast<const float4*>(&sBt[j0*BPAD]);
            const float4* Bp1 = reinterpret_cast<const float4*>(&sBt[j1*BPAD]);

            float h2a[NH2], h2b[NH2];
            #pragma unroll
            for (int k = 0; k < NH2; k++) { h2a[k] = sb2[k]; h2b[k] = 0.f; }

            #pragma unroll 1
            for (int v = 0; v < 16; v++) {
                float4 av = sA4[v];
                float4 wv = we4[v];
                float4 b0 = Bp0[v];
                float4 b1 = Bp1[v];
                float ta0 = fmaxf(av.x + fmaf(e0, wv.x, b0.x), 0.f);
                float ta1 = fmaxf(av.y + fmaf(e0, wv.y, b0.y), 0.f);
                float ta2 = fmaxf(av.z + fmaf(e0, wv.z, b0.z), 0.f);
                float ta3 = fmaxf(av.w + fmaf(e0, wv.w, b0.w), 0.f);
                float tb0 = fmaxf(av.x + fmaf(e1, wv.x, b1.x), 0.f);
                float tb1 = fmaxf(av.y + fmaf(e1, wv.y, b1.y), 0.f);
                float tb2 = fmaxf(av.z + fmaf(e1, wv.z, b1.z), 0.f);
                float tb3 = fmaxf(av.w + fmaf(e1, wv.w, b1.w), 0.f);
                #pragma unroll
                for (int q = 0; q < 8; q++) {
                    float4 wq = sW24[(4*v+0)*8 + q];
                    h2a[4*q+0] = fmaf(ta0, wq.x, h2a[4*q+0]);
                    h2a[4*q+1] = fmaf(ta0, wq.y, h2a[4*q+1]);
                    h2a[4*q+2] = fmaf(ta0, wq.z, h2a[4*q+2]);
                    h2a[4*q+3] = fmaf(ta0, wq.w, h2a[4*q+3]);
                    h2b[4*q+0] = fmaf(tb0, wq.x, h2b[4*q+0]);
                    h2b[4*q+1] = fmaf(tb0, wq.y, h2b[4*q+1]);
                    h2b[4*q+2] = fmaf(tb0, wq.z, h2b[4*q+2]);
                    h2b[4*q+3] = fmaf(tb0, wq.w, h2b[4*q+3]);
                }
                #pragma unroll
                for (int q = 0; q < 8; q++) {
                    float4 wq = sW24[(4*v+1)*8 + q];
                    h2a[4*q+0] = fmaf(ta1, wq.x, h2a[4*q+0]);
                    h2a[4*q+1] = fmaf(ta1, wq.y, h2a[4*q+1]);
                    h2a[4*q+2] = fmaf(ta1, wq.z, h2a[4*q+2]);
                    h2a[4*q+3] = fmaf(ta1, wq.w, h2a[4*q+3]);
                    h2b[4*q+0] = fmaf(tb1, wq.x, h2b[4*q+0]);
                    h2b[4*q+1] = fmaf(tb1, wq.y, h2b[4*q+1]);
                    h2b[4*q+2] = fmaf(tb1, wq.z, h2b[4*q+2]);
                    h2b[4*q+3] = fmaf(tb1, wq.w, h2b[4*q+3]);
                }
                #pragma unroll
                for (int q = 0; q < 8; q++) {
                    float4 wq = sW24[(4*v+2)*8 + q];
                    h2a[4*q+0] = fmaf(ta2, wq.x, h2a[4*q+0]);
                    h2a[4*q+1] = fmaf(ta2, wq.y, h2a[4*q+1]);
                    h2a[4*q+2] = fmaf(ta2, wq.z, h2a[4*q+2]);
                    h2a[4*q+3] = fmaf(ta2, wq.w, h2a[4*q+3]);
                    h2b[4*q+0] = fmaf(tb2, wq.x, h2b[4*q+0]);
                    h2b[4*q+1] = fmaf(tb2, wq.y, h2b[4*q+1]);
                    h2b[4*q+2] = fmaf(tb2, wq.z, h2b[4*q+2]);
                    h2b[4*q+3] = fmaf(tb2, wq.w, h2b[4*q+3]);
                }
                #pragma unroll
                for (int q = 0; q < 8; q++) {
                    float4 wq = sW24[(4*v+3)*8 + q];
                    h2a[4*q+0] = fmaf(ta3, wq.x, h2a[4*q+0]);
                    h2a[4*q+1] = fmaf(ta3, wq.y, h2a[4*q+1]);
                    h2a[4*q+2] = fmaf(ta3, wq.z, h2a[4*q+2]);
                    h2a[4*q+3] = fmaf(ta3, wq.w, h2a[4*q+3]);
                    h2b[4*q+0] = fmaf(tb3, wq.x, h2b[4*q+0]);
                    h2b[4*q+1] = fmaf(tb3, wq.y, h2b[4*q+1]);
                    h2b[4*q+2] = fmaf(tb3, wq.z, h2b[4*q+2]);
                    h2b[4*q+3] = fmaf(tb3, wq.w, h2b[4*q+3]);
                }
            }

            // alphas
            float bt0 = si + sSj[j0];
            bt0 = bt0 > 0.f ? bt0 : 0.2f*bt0;
            float al0 = __expf(bt0 - mx) * invd;
            float al1 = 0.f;
            if (s1ok) {
                float bt1 = si + sSj[j1];
                bt1 = bt1 > 0.f ? bt1 : 0.2f*bt1;
                al1 = __expf(bt1 - mx) * invd;
            }
            #pragma unroll
            for (int k = 0; k < NH2; k++) {
                p[k] = fmaf(al0, fmaxf(h2a[k], 0.f), p[k]);
                p[k] = fmaf(al1, fmaxf(h2b[k] + sb2[k], 0.f), p[k]);
            }
        }
    }

    // warp reduce p over lanes
    #pragma unroll
    for (int o = 16; o; o >>= 1) {
        #pragma unroll
        for (int k = 0; k < NH2; k++)
            p[k] += __shfl_xor_sync(0xffffffffu, p[k], o);
    }

    // GRU update (lanes 0..7, lane = feature). agg = p @ W3 + b3*(cnt>0)
    if (lane < FF) {
        int f = lane;
        int node = row;
        int cnt = s_toff[w*5 + 4];
        float haveN = (cnt > 0) ? 1.f : 0.f;
        float acc = sb3[f] * haveN;
        #pragma unroll
        for (int k = 0; k < NH2; k++) acc = fmaf(p[k], sW3[k*FF + f], acc);
        float agg_f = acc;

        // gather full agg[8] via shfl (lanes 0..7 hold features 0..7)
        float agg[FF];
        #pragma unroll
        for (int x = 0; x < FF; x++)
            agg[x] = __shfl_sync(0x000000ffu, agg_f, x);

        const float* uin  = (t == 0) ? u0 : g_u[t & 1];
        float*       uout = g_u[(t + 1) & 1];
        float uo = uin[node*FF + f];
        float gir = sbih[f], giz = sbih[f+8], gin = sbih[f+16];
        #pragma unroll
        for (int x = 0; x < FF; x++) {
            float ax = agg[x];
            gir = fmaf(ax, sWih[x*24 + f     ], gir);
            giz = fmaf(ax, sWih[x*24 + f +  8], giz);
            gin = fmaf(ax, sWih[x*24 + f + 16], gin);
        }
        float ghr = g_gh[(size_t)node*24 + f     ];
        float ghz = g_gh[(size_t)node*24 + f +  8];
        float ghn = g_gh[(size_t)node*24 + f + 16];
        float r  = 1.f/(1.f + __expf(-(gir + ghr)));
        float z  = 1.f/(1.f + __expf(-(giz + ghz)));
        float nn = tanhf(fmaf(r, ghn, gin));
        uout[node*FF + f] = (1.f - z)*nn + z*uo;
    }
}

// ---------------- readout ----------------
__global__ void k_readout(const float* __restrict__ W1, const float* __restrict__ b1,
                          const float* __restrict__ W2, const float* __restrict__ b2,
                          const float* __restrict__ W3, const float* __restrict__ b3,
                          float* __restrict__ out)
{
    __shared__ float sW1[FF*NH1], sb1[NH1], sW2[NH1*NH2], sb2[NH2], sW3[NH2*NS], sb3[NS];
    int tid = threadIdx.x;
    for (int x = tid; x < FF*NH1;  x += blockDim.x) sW1[x] = W1[x];
    for (int x = tid; x < NH1*NH2; x += blockDim.x) sW2[x] = W2[x];
    for (int x = tid; x < NH2*NS;  x += blockDim.x) sW3[x] = W3[x];
    if (tid < NH1) sb1[tid] = b1[tid];
    if (tid < NH2) sb2[tid] = b2[tid];
    if (tid < NS)  sb3[tid] = b3[tid];
    __syncthreads();

    int node = blockIdx.x * blockDim.x + tid;
    float u[FF];
    #pragma unroll
    for (int x = 0; x < FF; x++) u[x] = g_u[0][node*FF + x];

    float h2[NH2];
    #pragma unroll
    for (int k = 0; k < NH2; k++) h2[k] = sb2[k];
    for (int m = 0; m < NH1; m++) {
        float h1 = sb1[m];
        #pragma unroll
        for (int x = 0; x < FF; x++) h1 = fmaf(u[x], sW1[x*NH1 + m], h1);
        h1 = fmaxf(h1, 0.f);
        #pragma unroll
        for (int k = 0; k < NH2; k++) h2[k] = fmaf(h1, sW2[m*NH2 + k], h2[k]);
    }
    float l0 = sb3[0], l1 = sb3[1];
    #pragma unroll
    for (int k = 0; k < NH2; k++) {
        float x = fmaxf(h2[k], 0.f);
        l0 = fmaf(x, sW3[k*NS + 0], l0);
        l1 = fmaf(x, sW3[k*NS + 1], l1);
    }
    out[node*NS + 0] = l0;
    out[node*NS + 1] = l1;
}

// ---------------- launch ----------------
extern "C" void kernel_launch(void* const* d_in, const int* in_sizes, int n_in,
                              void* d_out, int out_size)
{
    (void)in_sizes; (void)n_in; (void)out_size;
    const float* u0     = (const float*)d_in[0];
    const int*   adj    = (const int*)  d_in[1];
    const float* ef     = (const float*)d_in[2];
    const float* sigma2 = (const float*)d_in[3];
    const float* Wattn  = (const float*)d_in[4];
    const float* al     = (const float*)d_in[5];
    const float* ar     = (const float*)d_in[6];
    const float* mW1    = (const float*)d_in[7];
    const float* mb1    = (const float*)d_in[8];
    const float* mW2    = (const float*)d_in[9];
    const float* mb2    = (const float*)d_in[10];
    const float* mW3    = (const float*)d_in[11];
    const float* mb3    = (const float*)d_in[12];
    const float* Wih    = (const float*)d_in[13];
    const float* Whh    = (const float*)d_in[14];
    const float* bih    = (const float*)d_in[15];
    const float* bhh    = (const float*)d_in[16];
    const float* rW1    = (const float*)d_in[17];
    const float* rb1    = (const float*)d_in[18];
    const float* rW2    = (const float*)d_in[19];
    const float* rb2    = (const float*)d_in[20];
    const float* rW3    = (const float*)d_in[21];
    const float* rb3    = (const float*)d_in[22];
    float* out = (float*)d_out;

    k_compact<<<NB*NN/4, 128>>>(adj, ef);
    for (int t = 0; t < TIT; t++) {
        k_node<<<32, 128>>>(u0, Wattn, al, ar, mW1, mb1, Whh, bhh, sigma2, t);
        k_soft<<<NB*NN/4, 128>>>();
        k_edge<<<NB*NN/8, 256>>>(u0, mW1, mW2, mb2, mW3, mb3, Wih, bih, t);
    }
    k_readout<<<32, 128>>>(rW1, rb1, rW2, rb2, rW3, rb3, out);
}

// round 9
// speedup vs baseline: 1.4532x; 1.4532x over previous
#include <cuda_runtime.h>
#include <math.h>

#define NB   8
#define NN   512
#define FF   8
#define FP   16
#define NH1  64
#define NH2  32
#define NS   2
#define TIT  10

// ---------------- scratch (no allocations allowed) ----------------
__device__ __align__(256) float  g_A  [NB*NN*NH1];   // u_i @ W1a + sigma*w1s + b1
__device__ __align__(256) float4 g_Bv [16*NB*NN];    // u_j @ W1b, v-major: [v][node] 16B chunks
__device__ __align__(256) float  g_si [NB*NN];
__device__ __align__(256) float  g_sj [NB*NN];
__device__ __align__(256) float  g_mx [NB*NN];
__device__ __align__(256) float  g_invd[NB*NN];
__device__ __align__(256) float  g_gh [NB*NN*24];    // u @ Whh + bhh
__device__ __align__(256) float  g_u  [2][NB*NN*FF]; // ping-pong state
__device__ __align__(256) unsigned short g_nbr[NB*NN*NN]; // compacted neighbor idx (sorted)
__device__ __align__(256) float  g_ec [NB*NN*NN];    // compacted edge feat
__device__ __align__(256) int    g_cnt[NB*NN];

// ---------------- adjacency compaction (runs once; adj static) ----------------
__global__ void k_compact(const int* __restrict__ adj, const float* __restrict__ ef)
{
    int warp = (blockIdx.x * blockDim.x + threadIdx.x) >> 5;
    int lane = threadIdx.x & 31;
    if (warp >= NB*NN) return;
    const int*   arow = adj + (size_t)warp * NN;
    const float* erow = ef  + (size_t)warp * NN;
    int base = 0;
    #pragma unroll
    for (int c = 0; c < NN/32; c++) {
        int jj = c*32 + lane;
        int a  = arow[jj];
        unsigned bal = __ballot_sync(0xffffffffu, a > 0);
        if (a > 0) {
            int pos = base + __popc(bal & ((1u << lane) - 1u));
            g_nbr[(size_t)warp*NN + pos] = (unsigned short)jj;
            g_ec [(size_t)warp*NN + pos] = erow[jj];
        }
        base += __popc(bal);
    }
    if (lane == 0) g_cnt[warp] = base;
}

// ---------------- per-node precompute ----------------
__global__ void k_node(const float* __restrict__ u0,
                       const float* __restrict__ Wattn,
                       const float* __restrict__ al, const float* __restrict__ ar,
                       const float* __restrict__ W1, const float* __restrict__ b1,
                       const float* __restrict__ Whh, const float* __restrict__ bhh,
                       const float* __restrict__ sigma2, int t)
{
    __shared__ float sWa[FF*FP], sal[FP], sar[FP];
    __shared__ float sW1a[FF*NH1], sW1b[FF*NH1], sw1s[NH1], sb1[NH1];
    __shared__ float sWhh[FF*24], sbhh[24];
    int tid = threadIdx.x;
    for (int x = tid; x < FF*FP; x += blockDim.x) sWa[x] = Wattn[x];
    if (tid < FP) { sal[tid] = al[tid]; sar[tid] = ar[tid]; }
    for (int x = tid; x < FF*NH1; x += blockDim.x) {
        sW1a[x] = W1[x];
        sW1b[x] = W1[FF*NH1 + x];
    }
    if (tid < NH1) { sw1s[tid] = W1[17*NH1 + tid]; sb1[tid] = b1[tid]; }
    for (int x = tid; x < FF*24; x += blockDim.x) sWhh[x] = Whh[x];
    if (tid < 24) sbhh[tid] = bhh[tid];
    __syncthreads();

    int node = blockIdx.x * blockDim.x + tid;   // 4096 nodes
    int b = node >> 9;
    const float* uin = (t == 0) ? u0 : g_u[t & 1];
    float u[FF];
    #pragma unroll
    for (int x = 0; x < FF; x++) u[x] = uin[node*FF + x];
    float sg = sigma2[b];

    // attention scores (split-a)
    float si = 0.f, sj = 0.f;
    #pragma unroll
    for (int p = 0; p < FP; p++) {
        float acc = 0.f;
        #pragma unroll
        for (int x = 0; x < FF; x++) acc = fmaf(u[x], sWa[x*FP + p], acc);
        si = fmaf(acc, sal[p], si);
        sj = fmaf(acc, sar[p], sj);
    }
    g_si[node] = si; g_sj[node] = sj;

    // A rows (node-major) + B rows (v-major float4 planes, coalesced writes)
    float bb[NH1];
    for (int m = 0; m < NH1; m++) {
        float a  = fmaf(sg, sw1s[m], sb1[m]);
        float b2 = 0.f;
        #pragma unroll
        for (int x = 0; x < FF; x++) {
            a  = fmaf(u[x], sW1a[x*NH1 + m], a);
            b2 = fmaf(u[x], sW1b[x*NH1 + m], b2);
        }
        g_A[(size_t)node*NH1 + m] = a;
        bb[m] = b2;
    }
    #pragma unroll
    for (int v = 0; v < 16; v++)
        g_Bv[v*(NB*NN) + node] = make_float4(bb[4*v+0], bb[4*v+1], bb[4*v+2], bb[4*v+3]);

    // gh = u @ Whh + bhh
    for (int g = 0; g < 24; g++) {
        float acc = sbhh[g];
        #pragma unroll
        for (int x = 0; x < FF; x++) acc = fmaf(u[x], sWhh[x*24 + g], acc);
        g_gh[(size_t)node*24 + g] = acc;
    }
}

// ---------------- softmax stats per row ----------------
__global__ void k_soft()
{
    int warp = (blockIdx.x * blockDim.x + threadIdx.x) >> 5;
    int lane = threadIdx.x & 31;
    if (warp >= NB*NN) return;
    int b = warp >> 9;
    int cnt = g_cnt[warp];
    float si = g_si[warp];
    const unsigned short* nb = g_nbr + (size_t)warp*NN;
    const float* sjb = g_sj + b*NN;

    float mx = -3.4e38f;
    for (int s = lane; s < cnt; s += 32) {
        float bt = si + sjb[nb[s]];
        bt = bt > 0.f ? bt : 0.2f*bt;
        mx = fmaxf(mx, bt);
    }
    #pragma unroll
    for (int o = 16; o; o >>= 1) mx = fmaxf(mx, __shfl_xor_sync(0xffffffffu, mx, o));
    float sm = 0.f;
    for (int s = lane; s < cnt; s += 32) {
        float bt = si + sjb[nb[s]];
        bt = bt > 0.f ? bt : 0.2f*bt;
        sm += __expf(bt - mx);
    }
    #pragma unroll
    for (int o = 16; o; o >>= 1) sm += __shfl_xor_sync(0xffffffffu, sm, o);
    if (lane == 0) {
        g_mx  [warp] = (cnt > 0) ? mx : 0.f;
        g_invd[warp] = (cnt > 0) ? (1.f/sm) : 0.f;
    }
}

// ---------------- fused edge MLP + aggregate + GRU ----------------
// block = 256 threads = 8 warps; warp w owns node i = i_base + w.
// B is stored v-major (g_Bv[v][node]): at step v, a warp's 32 sorted-j gathers
// span ~64 consecutive nodes -> ~8 L1 lines per LDG.128 instead of ~32.
// 2-edge-per-lane register blocking amortizes the broadcast W2 LDS.
// Layer-3 folded: agg = (sum_e a_e relu(h2_e)) @ W3 + b3*[cnt>0]
__global__ void __launch_bounds__(256, 2) k_edge(
    const float* __restrict__ u0,
    const float* __restrict__ W1,
    const float* __restrict__ W2, const float* __restrict__ b2,
    const float* __restrict__ W3, const float* __restrict__ b3,
    const float* __restrict__ Wih, const float* __restrict__ bih, int t)
{
    __shared__ __align__(16) float sW2[NH1*NH2];   // 8 KB
    __shared__ __align__(16) float sW3[NH2*FF];
    __shared__ __align__(16) float sA [8*NH1];
    __shared__ __align__(16) float sw1e[NH1];
    __shared__ float sSj[NN];                      // 2 KB staged sj
    __shared__ float sb2[NH2], sb3[FF];
    __shared__ float s_si[8], s_mx[8], s_invd[8];
    __shared__ int   s_cnt[8];
    __shared__ float sWih[FF*24], sbih[24];

    int tid = threadIdx.x;
    int bx  = blockIdx.x;
    int b   = bx >> 6;
    int i_base = (bx & 63) * 8;
    int rowbase = b*NN + i_base;

    for (int x = tid; x < NH1*NH2; x += 256) sW2[x] = W2[x];
    for (int x = tid; x < NH2*FF;  x += 256) sW3[x] = W3[x];
    if (tid < NH2) sb2[tid] = b2[tid];
    if (tid < FF)  sb3[tid] = b3[tid];
    if (tid < NH1) sw1e[tid] = W1[16*NH1 + tid];
    for (int x = tid; x < 8*NH1; x += 256) sA[x] = g_A[(size_t)rowbase*NH1 + x];
    if (tid < 8) {
        s_si  [tid] = g_si  [rowbase + tid];
        s_mx  [tid] = g_mx  [rowbase + tid];
        s_invd[tid] = g_invd[rowbase + tid];
        s_cnt [tid] = g_cnt [rowbase + tid];
    }
    for (int x = tid; x < NN; x += 256) sSj[x] = g_sj[b*NN + x];
    for (int x = tid; x < FF*24; x += 256) sWih[x] = Wih[x];
    if (tid < 24) sbih[tid] = bih[tid];
    __syncthreads();

    int w    = tid >> 5;
    int lane = tid & 31;
    int row  = rowbase + w;
    int cnt  = s_cnt[w];
    float si = s_si[w], mx = s_mx[w], invd = s_invd[w];
    const float4* sA4  = reinterpret_cast<const float4*>(&sA[w*NH1]);
    const float4* we4  = reinterpret_cast<const float4*>(sw1e);
    const float4* sW24 = reinterpret_cast<const float4*>(sW2);
    const unsigned short* nb = g_nbr + (size_t)row*NN;
    const float* ec  = g_ec + (size_t)row*NN;

    // p = sum_e alpha_e * relu(h2_e)
    float p[NH2];
    #pragma unroll
    for (int k = 0; k < NH2; k++) p[k] = 0.f;

    for (int s0 = lane; s0 < cnt; s0 += 64) {
        int  s1ok = (s0 + 32) < cnt;
        int  j0   = nb[s0];
        int  j1   = s1ok ? nb[s0 + 32] : j0;
        float e0  = ec[s0];
        float e1  = s1ok ? ec[s0 + 32] : 0.f;
        int  jb0  = b*NN + j0;
        int  jb1  = b*NN + j1;

        float h2a[NH2], h2b[NH2];
        #pragma unroll
        for (int k = 0; k < NH2; k++) { h2a[k] = sb2[k]; h2b[k] = 0.f; }

        #pragma unroll 1
        for (int v = 0; v < 16; v++) {
            float4 av = sA4[v];
            float4 wv = we4[v];
            float4 b0 = g_Bv[v*(NB*NN) + jb0];
            float4 b1 = g_Bv[v*(NB*NN) + jb1];
            float ta0 = fmaxf(av.x + fmaf(e0, wv.x, b0.x), 0.f);
            float ta1 = fmaxf(av.y + fmaf(e0, wv.y, b0.y), 0.f);
            float ta2 = fmaxf(av.z + fmaf(e0, wv.z, b0.z), 0.f);
            float ta3 = fmaxf(av.w + fmaf(e0, wv.w, b0.w), 0.f);
            float tb0 = fmaxf(av.x + fmaf(e1, wv.x, b1.x), 0.f);
            float tb1 = fmaxf(av.y + fmaf(e1, wv.y, b1.y), 0.f);
            float tb2 = fmaxf(av.z + fmaf(e1, wv.z, b1.z), 0.f);
            float tb3 = fmaxf(av.w + fmaf(e1, wv.w, b1.w), 0.f);
            #pragma unroll
            for (int q = 0; q < 8; q++) {
                float4 wq = sW24[(4*v+0)*8 + q];
                h2a[4*q+0] = fmaf(ta0, wq.x, h2a[4*q+0]);
                h2a[4*q+1] = fmaf(ta0, wq.y, h2a[4*q+1]);
                h2a[4*q+2] = fmaf(ta0, wq.z, h2a[4*q+2]);
                h2a[4*q+3] = fmaf(ta0, wq.w, h2a[4*q+3]);
                h2b[4*q+0] = fmaf(tb0, wq.x, h2b[4*q+0]);
                h2b[4*q+1] = fmaf(tb0, wq.y, h2b[4*q+1]);
                h2b[4*q+2] = fmaf(tb0, wq.z, h2b[4*q+2]);
                h2b[4*q+3] = fmaf(tb0, wq.w, h2b[4*q+3]);
            }
            #pragma unroll
            for (int q = 0; q < 8; q++) {
                float4 wq = sW24[(4*v+1)*8 + q];
                h2a[4*q+0] = fmaf(ta1, wq.x, h2a[4*q+0]);
                h2a[4*q+1] = fmaf(ta1, wq.y, h2a[4*q+1]);
                h2a[4*q+2] = fmaf(ta1, wq.z, h2a[4*q+2]);
                h2a[4*q+3] = fmaf(ta1, wq.w, h2a[4*q+3]);
                h2b[4*q+0] = fmaf(tb1, wq.x, h2b[4*q+0]);
                h2b[4*q+1] = fmaf(tb1, wq.y, h2b[4*q+1]);
                h2b[4*q+2] = fmaf(tb1, wq.z, h2b[4*q+2]);
                h2b[4*q+3] = fmaf(tb1, wq.w, h2b[4*q+3]);
            }
            #pragma unroll
            for (int q = 0; q < 8; q++) {
                float4 wq = sW24[(4*v+2)*8 + q];
                h2a[4*q+0] = fmaf(ta2, wq.x, h2a[4*q+0]);
                h2a[4*q+1] = fmaf(ta2, wq.y, h2a[4*q+1]);
                h2a[4*q+2] = fmaf(ta2, wq.z, h2a[4*q+2]);
                h2a[4*q+3] = fmaf(ta2, wq.w, h2a[4*q+3]);
                h2b[4*q+0] = fmaf(tb2, wq.x, h2b[4*q+0]);
                h2b[4*q+1] = fmaf(tb2, wq.y, h2b[4*q+1]);
                h2b[4*q+2] = fmaf(tb2, wq.z, h2b[4*q+2]);
                h2b[4*q+3] = fmaf(tb2, wq.w, h2b[4*q+3]);
            }
            #pragma unroll
            for (int q = 0; q < 8; q++) {
                float4 wq = sW24[(4*v+3)*8 + q];
                h2a[4*q+0] = fmaf(ta3, wq.x, h2a[4*q+0]);
                h2a[4*q+1] = fmaf(ta3, wq.y, h2a[4*q+1]);
                h2a[4*q+2] = fmaf(ta3, wq.z, h2a[4*q+2]);
                h2a[4*q+3] = fmaf(ta3, wq.w, h2a[4*q+3]);
                h2b[4*q+0] = fmaf(tb3, wq.x, h2b[4*q+0]);
                h2b[4*q+1] = fmaf(tb3, wq.y, h2b[4*q+1]);
                h2b[4*q+2] = fmaf(tb3, wq.z, h2b[4*q+2]);
                h2b[4*q+3] = fmaf(tb3, wq.w, h2b[4*q+3]);
            }
        }

        // alphas
        float bt0 = si + sSj[j0];
        bt0 = bt0 > 0.f ? bt0 : 0.2f*bt0;
        float al0 = __expf(bt0 - mx) * invd;
        float al1 = 0.f;
        if (s1ok) {
            float bt1 = si + sSj[j1];
            bt1 = bt1 > 0.f ? bt1 : 0.2f*bt1;
            al1 = __expf(bt1 - mx) * invd;
        }
        #pragma unroll
        for (int k = 0; k < NH2; k++) {
            p[k] = fmaf(al0, fmaxf(h2a[k], 0.f), p[k]);
            p[k] = fmaf(al1, fmaxf(h2b[k] + sb2[k], 0.f), p[k]);
        }
    }

    // warp reduce p over lanes
    #pragma unroll
    for (int o = 16; o; o >>= 1) {
        #pragma unroll
        for (int k = 0; k < NH2; k++)
            p[k] += __shfl_xor_sync(0xffffffffu, p[k], o);
    }

    // GRU update (lanes 0..7, lane = feature). agg = p @ W3 + b3*(cnt>0)
    if (lane < FF) {
        int f = lane;
        int node = row;
        float haveN = (cnt > 0) ? 1.f : 0.f;
        float acc = sb3[f] * haveN;
        #pragma unroll
        for (int k = 0; k < NH2; k++) acc = fmaf(p[k], sW3[k*FF + f], acc);
        float agg_f = acc;

        // gather full agg[8] via shfl (lanes 0..7 hold features 0..7)
        float agg[FF];
        #pragma unroll
        for (int x = 0; x < FF; x++)
            agg[x] = __shfl_sync(0x000000ffu, agg_f, x);

        const float* uin  = (t == 0) ? u0 : g_u[t & 1];
        float*       uout = g_u[(t + 1) & 1];
        float uo = uin[node*FF + f];
        float gir = sbih[f], giz = sbih[f+8], gin = sbih[f+16];
        #pragma unroll
        for (int x = 0; x < FF; x++) {
            float ax = agg[x];
            gir = fmaf(ax, sWih[x*24 + f     ], gir);
            giz = fmaf(ax, sWih[x*24 + f +  8], giz);
            gin = fmaf(ax, sWih[x*24 + f + 16], gin);
        }
        float ghr = g_gh[(size_t)node*24 + f     ];
        float ghz = g_gh[(size_t)node*24 + f +  8];
        float ghn = g_gh[(size_t)node*24 + f + 16];
        float r  = 1.f/(1.f + __expf(-(gir + ghr)));
        float z  = 1.f/(1.f + __expf(-(giz + ghz)));
        float nn = tanhf(fmaf(r, ghn, gin));
        uout[node*FF + f] = (1.f - z)*nn + z*uo;
    }
}

// ---------------- readout ----------------
__global__ void k_readout(const float* __restrict__ W1, const float* __restrict__ b1,
                          const float* __restrict__ W2, const float* __restrict__ b2,
                          const float* __restrict__ W3, const float* __restrict__ b3,
                          float* __restrict__ out)
{
    __shared__ float sW1[FF*NH1], sb1[NH1], sW2[NH1*NH2], sb2[NH2], sW3[NH2*NS], sb3[NS];
    int tid = threadIdx.x;
    for (int x = tid; x < FF*NH1;  x += blockDim.x) sW1[x] = W1[x];
    for (int x = tid; x < NH1*NH2; x += blockDim.x) sW2[x] = W2[x];
    for (int x = tid; x < NH2*NS;  x += blockDim.x) sW3[x] = W3[x];
    if (tid < NH1) sb1[tid] = b1[tid];
    if (tid < NH2) sb2[tid] = b2[tid];
    if (tid < NS)  sb3[tid] = b3[tid];
    __syncthreads();

    int node = blockIdx.x * blockDim.x + tid;
    float u[FF];
    #pragma unroll
    for (int x = 0; x < FF; x++) u[x] = g_u[0][node*FF + x];

    float h2[NH2];
    #pragma unroll
    for (int k = 0; k < NH2; k++) h2[k] = sb2[k];
    for (int m = 0; m < NH1; m++) {
        float h1 = sb1[m];
        #pragma unroll
        for (int x = 0; x < FF; x++) h1 = fmaf(u[x], sW1[x*NH1 + m], h1);
        h1 = fmaxf(h1, 0.f);
        #pragma unroll
        for (int k = 0; k < NH2; k++) h2[k] = fmaf(h1, sW2[m*NH2 + k], h2[k]);
    }
    float l0 = sb3[0], l1 = sb3[1];
    #pragma unroll
    for (int k = 0; k < NH2; k++) {
        float x = fmaxf(h2[k], 0.f);
        l0 = fmaf(x, sW3[k*NS + 0], l0);
        l1 = fmaf(x, sW3[k*NS + 1], l1);
    }
    out[node*NS + 0] = l0;
    out[node*NS + 1] = l1;
}

// ---------------- launch ----------------
extern "C" void kernel_launch(void* const* d_in, const int* in_sizes, int n_in,
                              void* d_out, int out_size)
{
    (void)in_sizes; (void)n_in; (void)out_size;
    const float* u0     = (const float*)d_in[0];
    const int*   adj    = (const int*)  d_in[1];
    const float* ef     = (const float*)d_in[2];
    const float* sigma2 = (const float*)d_in[3];
    const float* Wattn  = (const float*)d_in[4];
    const float* al     = (const float*)d_in[5];
    const float* ar     = (const float*)d_in[6];
    const float* mW1    = (const float*)d_in[7];
    const float* mb1    = (const float*)d_in[8];
    const float* mW2    = (const float*)d_in[9];
    const float* mb2    = (const float*)d_in[10];
    const float* mW3    = (const float*)d_in[11];
    const float* mb3    = (const float*)d_in[12];
    const float* Wih    = (const float*)d_in[13];
    const float* Whh    = (const float*)d_in[14];
    const float* bih    = (const float*)d_in[15];
    const float* bhh    = (const float*)d_in[16];
    const float* rW1    = (const float*)d_in[17];
    const float* rb1    = (const float*)d_in[18];
    const float* rW2    = (const float*)d_in[19];
    const float* rb2    = (const float*)d_in[20];
    const float* rW3    = (const float*)d_in[21];
    const float* rb3    = (const float*)d_in[22];
    float* out = (float*)d_out;

    k_compact<<<NB*NN/4, 128>>>(adj, ef);
    for (int t = 0; t < TIT; t++) {
        k_node<<<32, 128>>>(u0, Wattn, al, ar, mW1, mb1, Whh, bhh, sigma2, t);
        k_soft<<<NB*NN/4, 128>>>();
        k_edge<<<NB*NN/8, 256>>>(u0, mW1, mW2, mb2, mW3, mb3, Wih, bih, t);
    }
    k_readout<<<32, 128>>>(rW1, rb1, rW2, rb2, rW3, rb3, out);
}